// round 12
// baseline (speedup 1.0000x reference)
#include <cuda_runtime.h>
#include <cuda_fp16.h>

#define BN 128   // n rows per block tile
#define BM 64    // m cols per block tile
#define TN 8     // n per thread
#define TM 4     // m per thread
#define DD 64    // feature dim
#define NDC 8    // double-chunks (8 dims = 16B each)
#define BNP (BN + BN / 8)   // padded x rows (conflict-free xr at TN=8)
#define THREADS 256

struct __align__(16) h2quad { __half2 a, b, c, d; };

// acc = v * 1.0 + acc  -> FFMA-imm (rt_SMSP=1)
__device__ __forceinline__ void ffma_acc1(float &acc, float v) {
    asm("fma.rn.f32 %0, %1, 0f3F800000, %0;" : "+f"(acc) : "f"(v));
}

__global__ __launch_bounds__(THREADS, 2)
void cdist_l1_kernel(const float4* __restrict__ x4,
                     const float4* __restrict__ w4,
                     float* __restrict__ out,
                     int Mtot, int ntiles, int ntm, int gridsz)
{
    __shared__ h2quad xs[NDC][BNP];  // 18KB (padded)
    __shared__ h2quad ws[NDC][BM];   // 8KB
    __shared__ float Sx[BN];
    __shared__ float Sw[BM];

    const int tid = threadIdx.x;
    const int tx = tid & 15;   // m: tx + j*16
    const int ty = tid >> 4;   // n: ty*8 + i  (padded slot ty*9 + i)

    for (int t = blockIdx.x; t < ntiles; t += gridsz) {
        const int n0 = (t / ntm) * BN;
        const int m0 = (t % ntm) * BM;

        // ---- load + convert x tile: 4 (n,dc) items per thread ----
        #pragma unroll
        for (int i = 0; i < (BN * NDC) / THREADS; i++) {   // 4
            int idx = tid + i * THREADS;
            int n  = idx & (BN - 1);
            int dc = idx >> 7;
            float4 v0 = x4[(size_t)(n0 + n) * 16 + dc * 2];
            float4 v1 = x4[(size_t)(n0 + n) * 16 + dc * 2 + 1];
            h2quad q;
            q.a = __floats2half2_rn(v0.x, v0.y);
            q.b = __floats2half2_rn(v0.z, v0.w);
            q.c = __floats2half2_rn(v1.x, v1.y);
            q.d = __floats2half2_rn(v1.z, v1.w);
            xs[dc][n + (n >> 3)] = q;
        }
        // ---- load + convert w tile: 2 per thread ----
        #pragma unroll
        for (int i = 0; i < (BM * NDC) / THREADS; i++) {   // 2
            int idx = tid + i * THREADS;
            int m  = idx & (BM - 1);
            int dc = idx >> 6;
            float4 v0 = w4[(size_t)(m0 + m) * 16 + dc * 2];
            float4 v1 = w4[(size_t)(m0 + m) * 16 + dc * 2 + 1];
            h2quad q;
            q.a = __floats2half2_rn(v0.x, v0.y);
            q.b = __floats2half2_rn(v0.z, v0.w);
            q.c = __floats2half2_rn(v1.x, v1.y);
            q.d = __floats2half2_rn(v1.z, v1.w);
            ws[dc][m] = q;
        }
        __syncthreads();

        // ---- fp32 row sums of the ROUNDED tiles ----
        if (tid < BN) {
            float s = 0.f;
            #pragma unroll
            for (int dc = 0; dc < NDC; dc++) {
                h2quad q = xs[dc][tid + (tid >> 3)];
                float2 fa = __half22float2(q.a), fb = __half22float2(q.b);
                float2 fc = __half22float2(q.c), fd = __half22float2(q.d);
                s += ((fa.x + fa.y) + (fb.x + fb.y)) + ((fc.x + fc.y) + (fd.x + fd.y));
            }
            Sx[tid] = s;
        } else if (tid < BN + BM) {
            int m = tid - BN;
            float s = 0.f;
            #pragma unroll
            for (int dc = 0; dc < NDC; dc++) {
                h2quad q = ws[dc][m];
                float2 fa = __half22float2(q.a), fb = __half22float2(q.b);
                float2 fc = __half22float2(q.c), fd = __half22float2(q.d);
                s += ((fa.x + fa.y) + (fb.x + fb.y)) + ((fc.x + fc.y) + (fd.x + fd.y));
            }
            Sw[m] = s;
        }

        float facc[TN][TM];
        #pragma unroll
        for (int i = 0; i < TN; i++)
            #pragma unroll
            for (int j = 0; j < TM; j++) facc[i][j] = 0.f;

        // 2 groups of 4 double-chunks (32 dims per fp16 group)
        #pragma unroll
        for (int g = 0; g < NDC / 4; g++) {
            __half2 hacc[TN][TM];
            #pragma unroll
            for (int h = 0; h < 4; h++) {
                const int dc = g * 4 + h;
                h2quad xr[TN], wr[TM];
                #pragma unroll
                for (int i = 0; i < TN; i++) xr[i] = xs[dc][ty * 9 + i];   // conflict-free
                #pragma unroll
                for (int j = 0; j < TM; j++) wr[j] = ws[dc][j * 16 + tx];  // conflict-free
                #pragma unroll
                for (int i = 0; i < TN; i++)
                    #pragma unroll
                    for (int j = 0; j < TM; j++) {
                        __half2 t0 = __hmax2(xr[i].a, wr[j].a);
                        __half2 t1 = __hmax2(xr[i].b, wr[j].b);
                        __half2 t2 = __hmax2(xr[i].c, wr[j].c);
                        __half2 t3 = __hmax2(xr[i].d, wr[j].d);
                        __half2 s  = __hadd2(__hadd2(t0, t1), __hadd2(t2, t3));
                        if (h == 0) hacc[i][j] = s;
                        else        hacc[i][j] = __hadd2(hacc[i][j], s);
                    }
            }
            // flush 32-dim partial to fp32
            #pragma unroll
            for (int i = 0; i < TN; i++)
                #pragma unroll
                for (int j = 0; j < TM; j++) {
                    float2 f = __half22float2(hacc[i][j]);
                    ffma_acc1(facc[i][j], f.x);
                    ffma_acc1(facc[i][j], f.y);
                }
        }

        __syncthreads();   // Sx/Sw written (pre-mainloop) -> visible to all

        // snapshot row sums to regs, then release smem before the STG epilogue
        float sxr[TN], swr[TM];
        #pragma unroll
        for (int i = 0; i < TN; i++) sxr[i] = Sx[ty * TN + i];
        #pragma unroll
        for (int j = 0; j < TM; j++) swr[j] = Sw[j * 16 + tx];

        __syncthreads();   // smem free for next tile's STS

        // ---- epilogue (global only; overlaps next tile's LDG) ----
        #pragma unroll
        for (int i = 0; i < TN; i++) {
            const size_t nrow = (size_t)(n0 + ty * TN + i) * (size_t)Mtot;
            #pragma unroll
            for (int j = 0; j < TM; j++) {
                out[nrow + m0 + j * 16 + tx] = fmaf(-2.f, facc[i][j], sxr[i] + swr[j]);
            }
        }
    }
}

extern "C" void kernel_launch(void* const* d_in, const int* in_sizes, int n_in,
                              void* d_out, int out_size) {
    const float4* x4 = (const float4*)d_in[0];   // [N, 64] fp32
    const float4* w4 = (const float4*)d_in[1];   // [M, 64] fp32
    float* out = (float*)d_out;                  // [N, M] fp32

    const int N = in_sizes[0] / DD;   // 8192
    const int M = in_sizes[1] / DD;   // 1024

    const int ntm = M / BM;                 // 16
    const int ntiles = (N / BN) * ntm;      // 1024

    static int nsm = 0;
    if (!nsm) {
        cudaDeviceGetAttribute(&nsm, cudaDevAttrMultiProcessorCount, 0);
        if (nsm <= 0) nsm = 148;
    }
    int grid = nsm * 2;                     // persistent: exactly one wave
    if (grid > ntiles) grid = ntiles;

    cdist_l1_kernel<<<grid, THREADS>>>(x4, w4, out, M, ntiles, ntm, grid);
}

// round 13
// speedup vs baseline: 1.0905x; 1.0905x over previous
#include <cuda_runtime.h>
#include <cuda_fp16.h>

#define BN 128   // n rows per block tile
#define BM 64    // m cols per block tile
#define TN 8     // n per thread
#define TM 4     // m per thread
#define DD 64    // feature dim
#define NDC 8    // double-chunks (8 dims = 16B each)
#define BNP (BN + BN / 8)   // padded x rows (conflict-free xr at TN=8)
#define THREADS 256
#define NMAX 8192
#define MMAX 1024

// fp32 row sums of the fp16-ROUNDED rows: [0,N) = x rows, [N, N+M) = w rows
__device__ float g_rowsum[NMAX + MMAX];

struct __align__(16) h2quad { __half2 a, b, c, d; };

// acc = v * 1.0 + acc  -> FFMA-imm (rt_SMSP=1)
__device__ __forceinline__ void ffma_acc1(float &acc, float v) {
    asm("fma.rn.f32 %0, %1, 0f3F800000, %0;" : "+f"(acc) : "f"(v));
}

__global__ void rowsum_kernel(const float4* __restrict__ x4,
                              const float4* __restrict__ w4,
                              int N, int M)
{
    int r = blockIdx.x * blockDim.x + threadIdx.x;
    if (r >= N + M) return;
    const float4* src = (r < N) ? (x4 + (size_t)r * 16)
                                : (w4 + (size_t)(r - N) * 16);
    float s = 0.f;
    #pragma unroll
    for (int c = 0; c < 16; c++) {
        float4 v = src[c];
        __half2 a = __floats2half2_rn(v.x, v.y);
        __half2 b = __floats2half2_rn(v.z, v.w);
        float2 fa = __half22float2(a), fb = __half22float2(b);
        s += (fa.x + fa.y) + (fb.x + fb.y);
    }
    g_rowsum[r] = s;
}

__global__ __launch_bounds__(THREADS, 2)
void cdist_l1_kernel(const float4* __restrict__ x4,
                     const float4* __restrict__ w4,
                     float* __restrict__ out,
                     int Mtot, int Ntot)
{
    __shared__ h2quad xs[NDC][BNP];  // 18KB (padded)
    __shared__ h2quad ws[NDC][BM];   // 8KB

    const int tid = threadIdx.x;
    const int n0 = blockIdx.y * BN;
    const int m0 = blockIdx.x * BM;
    const int tx = tid & 15;   // m: tx + j*16
    const int ty = tid >> 4;   // n: ty*8 + i  (padded slot ty*9 + i)

    // ---- issue row-sum LDGs early (L2-resident; consumed only in epilogue) ----
    float sxr[TN], swr[TM];
    #pragma unroll
    for (int i = 0; i < TN; i++) sxr[i] = g_rowsum[n0 + ty * TN + i];
    #pragma unroll
    for (int j = 0; j < TM; j++) swr[j] = g_rowsum[Ntot + m0 + j * 16 + tx];

    // ---- load + convert x tile: 4 (n,dc) items per thread ----
    #pragma unroll
    for (int i = 0; i < (BN * NDC) / THREADS; i++) {   // 4
        int idx = tid + i * THREADS;
        int n  = idx & (BN - 1);
        int dc = idx >> 7;
        float4 v0 = x4[(size_t)(n0 + n) * 16 + dc * 2];
        float4 v1 = x4[(size_t)(n0 + n) * 16 + dc * 2 + 1];
        h2quad q;
        q.a = __floats2half2_rn(v0.x, v0.y);
        q.b = __floats2half2_rn(v0.z, v0.w);
        q.c = __floats2half2_rn(v1.x, v1.y);
        q.d = __floats2half2_rn(v1.z, v1.w);
        xs[dc][n + (n >> 3)] = q;
    }
    // ---- load + convert w tile: 2 per thread ----
    #pragma unroll
    for (int i = 0; i < (BM * NDC) / THREADS; i++) {   // 2
        int idx = tid + i * THREADS;
        int m  = idx & (BM - 1);
        int dc = idx >> 6;
        float4 v0 = w4[(size_t)(m0 + m) * 16 + dc * 2];
        float4 v1 = w4[(size_t)(m0 + m) * 16 + dc * 2 + 1];
        h2quad q;
        q.a = __floats2half2_rn(v0.x, v0.y);
        q.b = __floats2half2_rn(v0.z, v0.w);
        q.c = __floats2half2_rn(v1.x, v1.y);
        q.d = __floats2half2_rn(v1.z, v1.w);
        ws[dc][m] = q;
    }
    __syncthreads();   // the only barrier in the kernel

    float facc[TN][TM];
    #pragma unroll
    for (int i = 0; i < TN; i++)
        #pragma unroll
        for (int j = 0; j < TM; j++) facc[i][j] = 0.f;

    // 2 groups of 4 double-chunks (32 dims per fp16 group)
    #pragma unroll
    for (int g = 0; g < NDC / 4; g++) {
        __half2 hacc[TN][TM];
        #pragma unroll
        for (int h = 0; h < 4; h++) {
            const int dc = g * 4 + h;
            h2quad xr[TN], wr[TM];
            #pragma unroll
            for (int i = 0; i < TN; i++) xr[i] = xs[dc][ty * 9 + i];   // conflict-free
            #pragma unroll
            for (int j = 0; j < TM; j++) wr[j] = ws[dc][j * 16 + tx];  // conflict-free
            #pragma unroll
            for (int i = 0; i < TN; i++)
                #pragma unroll
                for (int j = 0; j < TM; j++) {
                    __half2 t0 = __hmax2(xr[i].a, wr[j].a);
                    __half2 t1 = __hmax2(xr[i].b, wr[j].b);
                    __half2 t2 = __hmax2(xr[i].c, wr[j].c);
                    __half2 t3 = __hmax2(xr[i].d, wr[j].d);
                    __half2 s  = __hadd2(__hadd2(t0, t1), __hadd2(t2, t3));
                    if (h == 0) hacc[i][j] = s;
                    else        hacc[i][j] = __hadd2(hacc[i][j], s);
                }
        }
        // flush 32-dim partial to fp32
        #pragma unroll
        for (int i = 0; i < TN; i++)
            #pragma unroll
            for (int j = 0; j < TM; j++) {
                float2 f = __half22float2(hacc[i][j]);
                ffma_acc1(facc[i][j], f.x);
                ffma_acc1(facc[i][j], f.y);
            }
    }

    // ---- epilogue: out[n][m] = Sx[n] + Sw[m] - 2*sum_max ----
    #pragma unroll
    for (int i = 0; i < TN; i++) {
        const size_t nrow = (size_t)(n0 + ty * TN + i) * (size_t)Mtot;
        #pragma unroll
        for (int j = 0; j < TM; j++) {
            out[nrow + m0 + j * 16 + tx] = fmaf(-2.f, facc[i][j], sxr[i] + swr[j]);
        }
    }
}

extern "C" void kernel_launch(void* const* d_in, const int* in_sizes, int n_in,
                              void* d_out, int out_size) {
    const float4* x4 = (const float4*)d_in[0];   // [N, 64] fp32
    const float4* w4 = (const float4*)d_in[1];   // [M, 64] fp32
    float* out = (float*)d_out;                  // [N, M] fp32

    const int N = in_sizes[0] / DD;   // 8192
    const int M = in_sizes[1] / DD;   // 1024

    rowsum_kernel<<<(N + M + 255) / 256, 256>>>(x4, w4, N, M);

    dim3 grid(M / BM, N / BN);        // (16, 64)
    cdist_l1_kernel<<<grid, THREADS>>>(x4, w4, out, M, N);
}

// round 14
// speedup vs baseline: 1.1114x; 1.0191x over previous
#include <cuda_runtime.h>
#include <cuda_fp16.h>

#define BN 64    // n rows per block tile
#define BM 64    // m cols per block tile
#define TN 4     // n per thread
#define TM 4     // m per thread
#define DD 64    // feature dim
#define NDC 8    // double-chunks (8 dims = 16B each)
#define THREADS 256

struct __align__(16) h2quad { __half2 a, b, c, d; };

// acc = v * 1.0 + acc  -> FFMA-imm (rt_SMSP=1)
__device__ __forceinline__ void ffma_acc1(float &acc, float v) {
    asm("fma.rn.f32 %0, %1, 0f3F800000, %0;" : "+f"(acc) : "f"(v));
}

__device__ __forceinline__ float sum8(const h2quad &q) {
    float2 fa = __half22float2(q.a), fb = __half22float2(q.b);
    float2 fc = __half22float2(q.c), fd = __half22float2(q.d);
    return ((fa.x + fa.y) + (fb.x + fb.y)) + ((fc.x + fc.y) + (fd.x + fd.y));
}

__global__ __launch_bounds__(THREADS, 2)
void cdist_l1_kernel(const float4* __restrict__ x4,
                     const float4* __restrict__ w4,
                     float* __restrict__ out,
                     int Mtot)
{
    __shared__ h2quad xs[NDC][BN];   // 8KB
    __shared__ h2quad ws[NDC][BM];   // 8KB
    __shared__ float Sxp[4][BN];     // partial row sums (4 writers per row)
    __shared__ float Swp[4][BM];

    const int tid = threadIdx.x;
    const int n0 = blockIdx.y * BN;
    const int m0 = blockIdx.x * BM;
    const int tx = tid & 15;   // m: tx + j*16
    const int ty = tid >> 4;   // n: ty*4 + i

    // ---- load + convert x tile (2 items/thread), accumulate fp32 partial ----
    // item idx = tid + 256*i : n = idx&63 (same for both), dc = (tid>>6) + 4*i
    {
        const int n = tid & 63;
        const int w = tid >> 6;          // writer lane 0..3
        float px = 0.f;
        #pragma unroll
        for (int i = 0; i < 2; i++) {
            int dc = w + 4 * i;
            float4 v0 = x4[(size_t)(n0 + n) * 16 + dc * 2];
            float4 v1 = x4[(size_t)(n0 + n) * 16 + dc * 2 + 1];
            h2quad q;
            q.a = __floats2half2_rn(v0.x, v0.y);
            q.b = __floats2half2_rn(v0.z, v0.w);
            q.c = __floats2half2_rn(v1.x, v1.y);
            q.d = __floats2half2_rn(v1.z, v1.w);
            xs[dc][n] = q;
            px += sum8(q);               // fp32 sum of ROUNDED values
        }
        Sxp[w][n] = px;
    }
    // ---- load + convert w tile (2 items/thread), accumulate fp32 partial ----
    {
        const int m = tid & 63;
        const int w = tid >> 6;
        float pw = 0.f;
        #pragma unroll
        for (int i = 0; i < 2; i++) {
            int dc = w + 4 * i;
            float4 v0 = w4[(size_t)(m0 + m) * 16 + dc * 2];
            float4 v1 = w4[(size_t)(m0 + m) * 16 + dc * 2 + 1];
            h2quad q;
            q.a = __floats2half2_rn(v0.x, v0.y);
            q.b = __floats2half2_rn(v0.z, v0.w);
            q.c = __floats2half2_rn(v1.x, v1.y);
            q.d = __floats2half2_rn(v1.z, v1.w);
            ws[dc][m] = q;
            pw += sum8(q);
        }
        Swp[w][m] = pw;
    }
    __syncthreads();   // the only barrier

    float facc[TN][TM];
    #pragma unroll
    for (int i = 0; i < TN; i++)
        #pragma unroll
        for (int j = 0; j < TM; j++) facc[i][j] = 0.f;

    // 2 groups of 4 double-chunks (32 dims per fp16 group)
    #pragma unroll
    for (int g = 0; g < NDC / 4; g++) {
        __half2 hacc[TN][TM];
        #pragma unroll
        for (int h = 0; h < 4; h++) {
            const int dc = g * 4 + h;
            h2quad xr[TN], wr[TM];
            #pragma unroll
            for (int i = 0; i < TN; i++) xr[i] = xs[dc][ty * TN + i];  // 2-addr bcast
            #pragma unroll
            for (int j = 0; j < TM; j++) wr[j] = ws[dc][j * 16 + tx];  // conflict-free
            #pragma unroll
            for (int i = 0; i < TN; i++)
                #pragma unroll
                for (int j = 0; j < TM; j++) {
                    __half2 t0 = __hmax2(xr[i].a, wr[j].a);
                    __half2 t1 = __hmax2(xr[i].b, wr[j].b);
                    __half2 t2 = __hmax2(xr[i].c, wr[j].c);
                    __half2 t3 = __hmax2(xr[i].d, wr[j].d);
                    __half2 s  = __hadd2(__hadd2(t0, t1), __hadd2(t2, t3));
                    if (h == 0) hacc[i][j] = s;
                    else        hacc[i][j] = __hadd2(hacc[i][j], s);
                }
        }
        // flush 32-dim partial to fp32
        #pragma unroll
        for (int i = 0; i < TN; i++)
            #pragma unroll
            for (int j = 0; j < TM; j++) {
                float2 f = __half22float2(hacc[i][j]);
                ffma_acc1(facc[i][j], f.x);
                ffma_acc1(facc[i][j], f.y);
            }
    }

    // ---- combine row-sum partials (smem, post-sync-safe) ----
    float sxr[TN], swr[TM];
    #pragma unroll
    for (int i = 0; i < TN; i++) {
        int n = ty * TN + i;
        sxr[i] = (Sxp[0][n] + Sxp[1][n]) + (Sxp[2][n] + Sxp[3][n]);
    }
    #pragma unroll
    for (int j = 0; j < TM; j++) {
        int m = j * 16 + tx;
        swr[j] = (Swp[0][m] + Swp[1][m]) + (Swp[2][m] + Swp[3][m]);
    }

    // ---- epilogue: out[n][m] = Sx[n] + Sw[m] - 2*sum_max ----
    #pragma unroll
    for (int i = 0; i < TN; i++) {
        const size_t nrow = (size_t)(n0 + ty * TN + i) * (size_t)Mtot;
        #pragma unroll
        for (int j = 0; j < TM; j++) {
            out[nrow + m0 + j * 16 + tx] = fmaf(-2.f, facc[i][j], sxr[i] + swr[j]);
        }
    }
}

extern "C" void kernel_launch(void* const* d_in, const int* in_sizes, int n_in,
                              void* d_out, int out_size) {
    const float4* x4 = (const float4*)d_in[0];   // [N, 64] fp32
    const float4* w4 = (const float4*)d_in[1];   // [M, 64] fp32
    float* out = (float*)d_out;                  // [N, M] fp32

    const int N = in_sizes[0] / DD;   // 8192
    const int M = in_sizes[1] / DD;   // 1024

    dim3 grid(M / BM, N / BN);        // (16, 128) = 2048 blocks
    cdist_l1_kernel<<<grid, THREADS>>>(x4, w4, out, M);
}

// round 15
// speedup vs baseline: 1.1790x; 1.0608x over previous
#include <cuda_runtime.h>
#include <cuda_fp16.h>

#define BM 64
#define DD 64
#define NDC 8     // double-chunks (8 dims = 16B)
#define THREADS 256
// big tile: 128 rows, TN=8 ; small tile: 64 rows, TN=4
#define BNB 128
#define BNPB (BNB + BNB / 8)   // padded slots for big x tile

struct __align__(16) h2quad { __half2 a, b, c, d; };

__device__ __forceinline__ void ffma_acc1(float &acc, float v) {
    asm("fma.rn.f32 %0, %1, 0f3F800000, %0;" : "+f"(acc) : "f"(v));
}

__device__ __forceinline__ float sum8(const h2quad &q) {
    float2 fa = __half22float2(q.a), fb = __half22float2(q.b);
    float2 fc = __half22float2(q.c), fd = __half22float2(q.d);
    return ((fa.x + fa.y) + (fb.x + fb.y)) + ((fc.x + fc.y) + (fd.x + fd.y));
}

__device__ __forceinline__ h2quad cvt2(const float4 &v0, const float4 &v1) {
    h2quad q;
    q.a = __floats2half2_rn(v0.x, v0.y);
    q.b = __floats2half2_rn(v0.z, v0.w);
    q.c = __floats2half2_rn(v1.x, v1.y);
    q.d = __floats2half2_rn(v1.z, v1.w);
    return q;
}

__global__ __launch_bounds__(THREADS, 2)
void cdist_l1_kernel(const float4* __restrict__ x4,
                     const float4* __restrict__ w4,
                     float* __restrict__ out,
                     int Mtot, int nbig)
{
    __shared__ h2quad xs[NDC][BNPB];   // big path uses padded 144 slots; small uses first 64
    __shared__ h2quad ws[NDC][BM];
    __shared__ float Sxp[2][BNB];      // big: 2 writers/row; small reuses [0..1][0..63] with 2 writers
    __shared__ float Swp[4][BM];

    const int tid = threadIdx.x;
    const int m0 = blockIdx.x * BM;
    const int tx = tid & 15;
    const int ty = tid >> 4;

    // ---- w tile load (identical both paths): 2 items/thread ----
    {
        const int m = tid & 63;
        const int w = tid >> 6;
        float pw = 0.f;
        #pragma unroll
        for (int i = 0; i < 2; i++) {
            int dc = w + 4 * i;
            float4 v0 = w4[(size_t)(m0 + m) * 16 + dc * 2];
            float4 v1 = w4[(size_t)(m0 + m) * 16 + dc * 2 + 1];
            h2quad q = cvt2(v0, v1);
            ws[dc][m] = q;
            pw += sum8(q);
        }
        Swp[w][m] = pw;
    }

    if ((int)blockIdx.y < nbig) {
        // ================= BIG PATH: 128 x 64, TN=8 =================
        const int n0 = blockIdx.y * BNB;

        // x tile: 1024 items, 4/thread; n fixed per thread, dc = w + 2i
        {
            const int n = tid & 127;
            const int w = tid >> 7;                 // 0..1
            float px = 0.f;
            #pragma unroll
            for (int i = 0; i < 4; i++) {
                int dc = w + 2 * i;
                float4 v0 = x4[(size_t)(n0 + n) * 16 + dc * 2];
                float4 v1 = x4[(size_t)(n0 + n) * 16 + dc * 2 + 1];
                h2quad q = cvt2(v0, v1);
                xs[dc][n + (n >> 3)] = q;           // padded slot
                px += sum8(q);
            }
            Sxp[w][n] = px;
        }
        __syncthreads();

        float facc[8][4];
        #pragma unroll
        for (int i = 0; i < 8; i++)
            #pragma unroll
            for (int j = 0; j < 4; j++) facc[i][j] = 0.f;

        #pragma unroll
        for (int g = 0; g < 2; g++) {
            __half2 hacc[8][4];
            #pragma unroll
            for (int h = 0; h < 4; h++) {
                const int dc = g * 4 + h;
                h2quad xr[8], wr[4];
                #pragma unroll
                for (int i = 0; i < 8; i++) xr[i] = xs[dc][ty * 9 + i];
                #pragma unroll
                for (int j = 0; j < 4; j++) wr[j] = ws[dc][j * 16 + tx];
                #pragma unroll
                for (int i = 0; i < 8; i++)
                    #pragma unroll
                    for (int j = 0; j < 4; j++) {
                        __half2 t0 = __hmax2(xr[i].a, wr[j].a);
                        __half2 t1 = __hmax2(xr[i].b, wr[j].b);
                        __half2 t2 = __hmax2(xr[i].c, wr[j].c);
                        __half2 t3 = __hmax2(xr[i].d, wr[j].d);
                        __half2 s  = __hadd2(__hadd2(t0, t1), __hadd2(t2, t3));
                        if (h == 0) hacc[i][j] = s;
                        else        hacc[i][j] = __hadd2(hacc[i][j], s);
                    }
            }
            #pragma unroll
            for (int i = 0; i < 8; i++)
                #pragma unroll
                for (int j = 0; j < 4; j++) {
                    float2 f = __half22float2(hacc[i][j]);
                    ffma_acc1(facc[i][j], f.x);
                    ffma_acc1(facc[i][j], f.y);
                }
        }

        float sxr[8], swr[4];
        #pragma unroll
        for (int i = 0; i < 8; i++) {
            int n = ty * 8 + i;
            sxr[i] = Sxp[0][n] + Sxp[1][n];
        }
        #pragma unroll
        for (int j = 0; j < 4; j++) {
            int m = j * 16 + tx;
            swr[j] = (Swp[0][m] + Swp[1][m]) + (Swp[2][m] + Swp[3][m]);
        }
        #pragma unroll
        for (int i = 0; i < 8; i++) {
            const size_t nrow = (size_t)(n0 + ty * 8 + i) * (size_t)Mtot;
            #pragma unroll
            for (int j = 0; j < 4; j++)
                out[nrow + m0 + j * 16 + tx] = fmaf(-2.f, facc[i][j], sxr[i] + swr[j]);
        }
    } else {
        // ================= SMALL PATH: 64 x 64, TN=4 =================
        const int n0 = nbig * BNB + (blockIdx.y - nbig) * 64;

        // x tile: 512 items, 2/thread
        {
            const int n = tid & 63;
            const int w = tid >> 6;                 // 0..3 -> fold to 2 writer slots
            float px = 0.f;
            #pragma unroll
            for (int i = 0; i < 2; i++) {
                int dc = w + 4 * i;
                float4 v0 = x4[(size_t)(n0 + n) * 16 + dc * 2];
                float4 v1 = x4[(size_t)(n0 + n) * 16 + dc * 2 + 1];
                h2quad q = cvt2(v0, v1);
                xs[dc][n] = q;                      // unpadded (TN=4 xr is 2-addr bcast)
                px += sum8(q);
            }
            Sxp[w >> 1][n + (w & 1) * 64] = px;     // 2 writers/row packed into Sxp[2][128]
        }
        __syncthreads();

        float facc[4][4];
        #pragma unroll
        for (int i = 0; i < 4; i++)
            #pragma unroll
            for (int j = 0; j < 4; j++) facc[i][j] = 0.f;

        #pragma unroll
        for (int g = 0; g < 2; g++) {
            __half2 hacc[4][4];
            #pragma unroll
            for (int h = 0; h < 4; h++) {
                const int dc = g * 4 + h;
                h2quad xr[4], wr[4];
                #pragma unroll
                for (int i = 0; i < 4; i++) xr[i] = xs[dc][ty * 4 + i];
                #pragma unroll
                for (int j = 0; j < 4; j++) wr[j] = ws[dc][j * 16 + tx];
                #pragma unroll
                for (int i = 0; i < 4; i++)
                    #pragma unroll
                    for (int j = 0; j < 4; j++) {
                        __half2 t0 = __hmax2(xr[i].a, wr[j].a);
                        __half2 t1 = __hmax2(xr[i].b, wr[j].b);
                        __half2 t2 = __hmax2(xr[i].c, wr[j].c);
                        __half2 t3 = __hmax2(xr[i].d, wr[j].d);
                        __half2 s  = __hadd2(__hadd2(t0, t1), __hadd2(t2, t3));
                        if (h == 0) hacc[i][j] = s;
                        else        hacc[i][j] = __hadd2(hacc[i][j], s);
                    }
            }
            #pragma unroll
            for (int i = 0; i < 4; i++)
                #pragma unroll
                for (int j = 0; j < 4; j++) {
                    float2 f = __half22float2(hacc[i][j]);
                    ffma_acc1(facc[i][j], f.x);
                    ffma_acc1(facc[i][j], f.y);
                }
        }

        float sxr[4], swr[4];
        #pragma unroll
        for (int i = 0; i < 4; i++) {
            int n = ty * 4 + i;
            sxr[i] = (Sxp[0][n] + Sxp[0][n + 64]) + (Sxp[1][n] + Sxp[1][n + 64]);
        }
        #pragma unroll
        for (int j = 0; j < 4; j++) {
            int m = j * 16 + tx;
            swr[j] = (Swp[0][m] + Swp[1][m]) + (Swp[2][m] + Swp[3][m]);
        }
        #pragma unroll
        for (int i = 0; i < 4; i++) {
            const size_t nrow = (size_t)(n0 + ty * 4 + i) * (size_t)Mtot;
            #pragma unroll
            for (int j = 0; j < 4; j++)
                out[nrow + m0 + j * 16 + tx] = fmaf(-2.f, facc[i][j], sxr[i] + swr[j]);
        }
    }
}

extern "C" void kernel_launch(void* const* d_in, const int* in_sizes, int n_in,
                              void* d_out, int out_size) {
    const float4* x4 = (const float4*)d_in[0];   // [N, 64] fp32
    const float4* w4 = (const float4*)d_in[1];   // [M, 64] fp32
    float* out = (float*)d_out;                  // [N, M] fp32

    const int N = in_sizes[0] / DD;   // 8192
    const int M = in_sizes[1] / DD;   // 1024

    // mixed tiling: nbig 128-row tiles first, rest 64-row tiles.
    // N=8192: nbig=54, nsmall=20 -> 74*16 = 1184 blocks = 296*4 (occ-2 waves, no tail quant)
    int nbig, nsmall;
    if (N == 8192) { nbig = 54; nsmall = 20; }
    else { nbig = N / 128; nsmall = (N - nbig * 128) / 64; }

    dim3 grid(M / BM, nbig + nsmall);
    cdist_l1_kernel<<<grid, THREADS>>>(x4, w4, out, M, nbig);
}